// round 16
// baseline (speedup 1.0000x reference)
#include <cuda_runtime.h>
#include <cstdint>

#define DD    32          // embedding dim D
#define MM    32          // memories per hop
#define LEAKY 0.2f
#define RW    4           // ripple warps per block

// scratch: Rh[slot*D + d] for hop>=1 slots; hop-0 logits precomputed
__device__ float g_Rh[131072 * 32];
__device__ float g_logit0[131072];     // logit0[slot] for slot < B*M
__device__ int   g_dup[8192];          // dup[b]=1 if a later b' has same item

__device__ __forceinline__ float warpSum(float v) {
    #pragma unroll
    for (int off = 16; off; off >>= 1) v += __shfl_xor_sync(0xffffffffu, v, off);
    return v;
}
__device__ __forceinline__ float warpMax(float v) {
    #pragma unroll
    for (int off = 16; off; off >>= 1) v = fmaxf(v, __shfl_xor_sync(0xffffffffu, v, off));
    return v;
}
__device__ __forceinline__ void cp16(uint32_t saddr, const void* gaddr) {
    asm volatile("cp.async.cg.shared.global [%0], [%1], 16;" :: "r"(saddr), "l"(gaddr));
}

// ---------------------------------------------------------------------------
// MEGA kernel (R14 layout, measured best): blockIdx ranges select role.
//   [0, RB)        : r_all gather + fused Rh (warp-per-slot, 8 slots/block)
//                    hop-0 slots fold in item0 -> scalar logit0 (skip g_Rh)
//   [RB, RB+HB)    : h_all / t_all gather (float4 granularity)
//   [.., +CB)      : uEmbed + iEmbed contiguous copy (float4)
//   [.., +DB)      : dup-flag precompute for ripple (ALU-only, hidden)
// ZERO shared memory -> full 228KB L1D carveout -> rel table gets L1 hits.
// ---------------------------------------------------------------------------
__global__ void __launch_bounds__(256) mega_kernel(
        const int*    __restrict__ pos,
        const int*    __restrict__ mh,
        const int*    __restrict__ mr,
        const int*    __restrict__ mt,
        const float4* __restrict__ uE4,
        const float4* __restrict__ iE4,
        const float4* __restrict__ ent4,
        const float4* __restrict__ rel4,
        float4* __restrict__ out_u4,
        float4* __restrict__ out_h4,
        float4* __restrict__ out_t4,
        float4* __restrict__ out_r4,
        int HBM, int RB, int HB, int CB, int Ue4, int Ie4, int BM, int B) {
    int blk = blockIdx.x;
    const float* ent = (const float*)ent4;
    const float* iE  = (const float*)iE4;
    const unsigned FULL = 0xffffffffu;

    if (blk < RB) {
        int warp = threadIdx.x >> 5, lane = threadIdx.x & 31;
        int slot = blk * 8 + warp;
        if (slot >= HBM) return;

        int r = __ldg(&mr[slot]);
        const float4* src = rel4 + (size_t)r * 256;
        float4* dst = out_r4 + (size_t)slot * 256;

        float4 v[8];
        #pragma unroll
        for (int k = 0; k < 8; k++)       // 8 outstanding loads (L1/L2)
            v[k] = __ldg(&src[k * 32 + lane]);

        int e = __ldg(&mh[slot]);
        float hval = __ldg(&ent[(size_t)e * DD + lane]);

        int c4 = (lane & 7) * 4;
        float hx = __shfl_sync(FULL, hval, c4 + 0);
        float hy = __shfl_sync(FULL, hval, c4 + 1);
        float hz = __shfl_sync(FULL, hval, c4 + 2);
        float hw = __shfl_sync(FULL, hval, c4 + 3);

        float p[8];
        #pragma unroll
        for (int k = 0; k < 8; k++) {
            __stcs(&dst[k * 32 + lane], v[k]);   // streaming write-out
            p[k] = v[k].x * hx + v[k].y * hy + v[k].z * hz + v[k].w * hw;
        }
        #pragma unroll
        for (int k = 0; k < 8; k++) {
            p[k] += __shfl_xor_sync(FULL, p[k], 1);
            p[k] += __shfl_xor_sync(FULL, p[k], 2);
            p[k] += __shfl_xor_sync(FULL, p[k], 4);
        }
        int myk = lane & 7;
        float temp = p[0];
        #pragma unroll
        for (int k = 1; k < 8; k++) if (myk == k) temp = p[k];
        float acc = __shfl_sync(FULL, temp, ((lane & 3) << 3) + (lane >> 2));

        if (slot < BM) {
            int b = slot / MM;
            int p0 = __ldg(&pos[b]);
            float it0 = __ldg(&iE[(size_t)p0 * DD + lane]);
            float lg = warpSum(acc * it0);
            if (lane == 0) g_logit0[slot] = lg;
        } else {
            g_Rh[(size_t)slot * DD + lane] = acc;
        }
    } else if (blk < RB + HB) {
        int tid = (blk - RB) * 256 + threadIdx.x;
        int N = HBM * 8;
        if (tid < N) {
            int slot = tid >> 3, j = tid & 7;
            int e = __ldg(&mh[slot]);
            __stcs(&out_h4[slot * 8 + j], __ldg(&ent4[(size_t)e * 8 + j]));
        } else if (tid < 2 * N) {
            int t2 = tid - N;
            int slot = t2 >> 3, j = t2 & 7;
            int e = __ldg(&mt[slot]);
            float4 v = __ldg(&ent4[(size_t)e * 8 + j]);
            v.x = v.x > 0.f ? v.x : LEAKY * v.x;
            v.y = v.y > 0.f ? v.y : LEAKY * v.y;
            v.z = v.z > 0.f ? v.z : LEAKY * v.z;
            v.w = v.w > 0.f ? v.w : LEAKY * v.w;
            out_t4[slot * 8 + j] = v;
        }
    } else if (blk < RB + HB + CB) {
        int j = (blk - RB - HB) * 256 + threadIdx.x;
        if (j < Ue4)
            __stcs(&out_u4[j], __ldg(&uE4[j]));
        else if (j < Ue4 + Ie4)
            __stcs(&out_u4[j], __ldg(&iE4[j - Ue4]));
    } else {
        // ---- dup-flag precompute: one thread per batch row b ----
        int b = (blk - RB - HB - CB) * 256 + threadIdx.x;
        if (b < B) {
            int p = __ldg(&pos[b]);
            const int4* pos4 = (const int4*)pos;
            int dup = 0;
            for (int q = b >> 2; q < (B >> 2); q++) {   // int4-vectorized scan
                int4 v = __ldg(&pos4[q]);
                int base = q * 4;
                dup |= ((base + 0 > b) & (v.x == p));
                dup |= ((base + 1 > b) & (v.y == p));
                dup |= ((base + 2 > b) & (v.z == p));
                dup |= ((base + 3 > b) & (v.w == p));
            }
            g_dup[b] = dup;
        }
    }
}

// ---------------------------------------------------------------------------
// Ripple (R14 structure): one warp per b, 4 warps/block, 48KB smem. ALL
// memory the warp needs (hop-1 Rh, hop-0 t, hop-1 t = 24 lines) issued as
// cp.async at instruction 0. Dup resolution is now ONE broadcast load of
// the mega-precomputed flag (was a ~250-instruction scan per warp).
// ---------------------------------------------------------------------------
__global__ void __launch_bounds__(128) ripple_kernel(
        const int*   __restrict__ pos,
        const float* __restrict__ iE,
        const float* __restrict__ t_all,
        const float* __restrict__ W,
        float* __restrict__ out_i,
        int B, int nhop) {
    __shared__ float sRh[RW][MM * DD];   // 16KB
    __shared__ float sT0[RW][MM * DD];   // 16KB
    __shared__ float sT1[RW][MM * DD];   // 16KB  (total 48KB)
    const unsigned FULL = 0xffffffffu;
    int warp = threadIdx.x >> 5, lane = threadIdx.x & 31;
    int b = blockIdx.x * RW + warp;
    if (b >= B) return;
    int p = __ldg(&pos[b]);

    // issue ALL prefetches first: hop-1 Rh, hop-0 t, hop-1 t (24 cp.async)
    {
        const float4* Rh4 = (const float4*)(g_Rh + (size_t)(B + b) * MM * DD);
        const float4* T0  = (const float4*)(t_all + (size_t)b * MM * DD);
        const float4* T1  = (const float4*)(t_all + (size_t)(B + b) * MM * DD);
        uint32_t aR = (uint32_t)__cvta_generic_to_shared(&sRh[warp][0]);
        uint32_t a0 = (uint32_t)__cvta_generic_to_shared(&sT0[warp][0]);
        uint32_t a1 = (uint32_t)__cvta_generic_to_shared(&sT1[warp][0]);
        #pragma unroll
        for (int j = 0; j < 8; j++) {
            cp16(a0 + (j * 32 + lane) * 16, &T0[j * 32 + lane]);
            cp16(aR + (j * 32 + lane) * 16, &Rh4[j * 32 + lane]);
            cp16(a1 + (j * 32 + lane) * 16, &T1[j * 32 + lane]);
        }
        asm volatile("cp.async.commit_group;");
    }

    float logit = __ldg(&g_logit0[(size_t)b * MM + lane]);
    float item = __ldg(&iE[(size_t)p * DD + lane]);

    // last-wins: precomputed flag (one broadcast load, overlaps the asyncs)
    if (__ldg(&g_dup[b])) {
        asm volatile("cp.async.wait_group 0;" ::: "memory");  // drain safely
        return;
    }

    const float* myRh = sRh[warp];
    for (int hop = 0; hop < nhop; hop++) {
        if (hop > 0) {
            if (hop > 1) {   // generic fallback for nhop>2 (unused @nhop=2)
                float* dRh = sRh[warp];
                float* dT1 = sT1[warp];
                const float4* Rh4 =
                    (const float4*)(g_Rh + (size_t)(hop * B + b) * MM * DD);
                const float4* T4 =
                    (const float4*)(t_all + (size_t)(hop * B + b) * MM * DD);
                #pragma unroll
                for (int j = 0; j < 8; j++) {
                    ((float4*)dRh)[j * 32 + lane] = __ldg(&Rh4[j * 32 + lane]);
                    ((float4*)dT1)[j * 32 + lane] = __ldg(&T4[j * 32 + lane]);
                }
                __syncwarp();
            }
            // logit[m] on lane m from smem Rh x shuffled item, 4 partials
            float l0 = 0.f, l1 = 0.f, l2 = 0.f, l3 = 0.f;
            #pragma unroll
            for (int i = 0; i < DD; i += 4) {
                int e0 = (i + 0 + lane) & (DD - 1);
                int e1 = (i + 1 + lane) & (DD - 1);
                int e2 = (i + 2 + lane) & (DD - 1);
                int e3 = (i + 3 + lane) & (DD - 1);
                l0 = fmaf(myRh[lane * DD + e0], __shfl_sync(FULL, item, e0), l0);
                l1 = fmaf(myRh[lane * DD + e1], __shfl_sync(FULL, item, e1), l1);
                l2 = fmaf(myRh[lane * DD + e2], __shfl_sync(FULL, item, e2), l2);
                l3 = fmaf(myRh[lane * DD + e3], __shfl_sync(FULL, item, e3), l3);
            }
            logit = (l0 + l1) + (l2 + l3);
        }
        // softmax across lanes
        float mx = warpMax(logit);
        float ex = expf(logit - mx);
        float prob = ex / warpSum(ex);

        if (hop == 0) {  // first consumption of smem tiles
            asm volatile("cp.async.wait_group 0;" ::: "memory");
            __syncwarp();
        }
        const float* tb = (hop == 0) ? sT0[warp] : sT1[warp];
        float o0 = 0.f, o1 = 0.f, o2 = 0.f, o3 = 0.f;
        #pragma unroll
        for (int m = 0; m < MM; m += 4) {
            float pa = __shfl_sync(FULL, prob, m + 0);
            float pb = __shfl_sync(FULL, prob, m + 1);
            float pc = __shfl_sync(FULL, prob, m + 2);
            float pd = __shfl_sync(FULL, prob, m + 3);
            o0 = fmaf(pa, tb[(m + 0) * DD + lane], o0);
            o1 = fmaf(pb, tb[(m + 1) * DD + lane], o1);
            o2 = fmaf(pc, tb[(m + 2) * DD + lane], o2);
            o3 = fmaf(pd, tb[(m + 3) * DD + lane], o3);
        }
        float o = (o0 + o1) + (o2 + o3);

        // item = (item + o) @ W.T : x broadcast via shuffle, W via L1 (__ldg)
        float x = item + o;
        float n0 = 0.f, n1 = 0.f, n2 = 0.f, n3 = 0.f;
        #pragma unroll
        for (int e = 0; e < DD; e += 4) {
            int e0 = (e + 0 + lane) & (DD - 1);
            int e1 = (e + 1 + lane) & (DD - 1);
            int e2 = (e + 2 + lane) & (DD - 1);
            int e3 = (e + 3 + lane) & (DD - 1);
            n0 = fmaf(__shfl_sync(FULL, x, e0), __ldg(&W[lane * DD + e0]), n0);
            n1 = fmaf(__shfl_sync(FULL, x, e1), __ldg(&W[lane * DD + e1]), n1);
            n2 = fmaf(__shfl_sync(FULL, x, e2), __ldg(&W[lane * DD + e2]), n2);
            n3 = fmaf(__shfl_sync(FULL, x, e3), __ldg(&W[lane * DD + e3]), n3);
        }
        item = (n0 + n1) + (n2 + n3);
    }
    __stcs(&out_i[(size_t)p * DD + lane], item);   // never re-read
}

// ---------------------------------------------------------------------------
extern "C" void kernel_launch(void* const* d_in, const int* in_sizes, int n_in,
                              void* d_out, int out_size) {
    const int*   pos = (const int*)d_in[0];
    const int*   mh  = (const int*)d_in[1];
    const int*   mr  = (const int*)d_in[2];
    const int*   mt  = (const int*)d_in[3];
    const float* uE  = (const float*)d_in[4];
    const float* iE  = (const float*)d_in[5];
    const float* ent = (const float*)d_in[6];
    const float* rel = (const float*)d_in[7];
    const float* W   = (const float*)d_in[8];
    float* out = (float*)d_out;

    const int B    = in_sizes[0];             // 2048
    const int HBM  = in_sizes[1];             // H*B*M = 131072
    const int nhop = HBM / (B * MM);          // 2
    const int BM   = B * MM;                  // 65536
    const size_t Ue = (size_t)in_sizes[4];    // USER*D floats
    const size_t Ie = (size_t)in_sizes[5];    // ITEM*D floats

    float* out_u = out;
    float* out_i = out_u + Ue;
    float* out_h = out_i + Ie;
    float* out_t = out_h + (size_t)HBM * DD;
    float* out_r = out_t + (size_t)HBM * DD;

    const int RB  = (HBM + 7) / 8;                      // 16384 r-blocks
    const int HB  = (2 * HBM * 8 + 255) / 256;          // 8192 ht-blocks
    const int Ue4 = (int)(Ue / 4), Ie4 = (int)(Ie / 4);
    const int CB  = (Ue4 + Ie4 + 255) / 256;            // 6250 copy-blocks
    const int DB  = (B + 255) / 256;                    // 8 dup-blocks

    mega_kernel<<<RB + HB + CB + DB, 256>>>(
        pos, mh, mr, mt,
        (const float4*)uE, (const float4*)iE,
        (const float4*)ent, (const float4*)rel,
        (float4*)out_u, (float4*)out_h, (float4*)out_t, (float4*)out_r,
        HBM, RB, HB, CB, Ue4, Ie4, BM, B);

    ripple_kernel<<<(B + RW - 1) / RW, 128>>>(pos, iE, out_t, W, out_i, B, nhop);
}

// round 17
// speedup vs baseline: 1.2065x; 1.2065x over previous
#include <cuda_runtime.h>
#include <cstdint>

#define DD    32          // embedding dim D
#define MM    32          // memories per hop
#define LEAKY 0.2f
#define RW    4           // ripple warps per block

// scratch: Rh[slot*D + d] for hop>=1 slots; hop-0 logits precomputed
__device__ float g_Rh[131072 * 32];
__device__ float g_logit0[131072];     // logit0[slot] for slot < B*M
__device__ int   g_dup[8192];          // dup[b]=1 if a later b' has same item

__device__ __forceinline__ float warpSum(float v) {
    #pragma unroll
    for (int off = 16; off; off >>= 1) v += __shfl_xor_sync(0xffffffffu, v, off);
    return v;
}
__device__ __forceinline__ float warpMax(float v) {
    #pragma unroll
    for (int off = 16; off; off >>= 1) v = fmaxf(v, __shfl_xor_sync(0xffffffffu, v, off));
    return v;
}
__device__ __forceinline__ void cp16(uint32_t saddr, const void* gaddr) {
    asm volatile("cp.async.cg.shared.global [%0], [%1], 16;" :: "r"(saddr), "l"(gaddr));
}

// ---------------------------------------------------------------------------
// MEGA kernel (R14 layout, measured best): blockIdx ranges select role.
//   [0, RB)        : r_all gather + fused Rh (warp-per-slot, 8 slots/block)
//                    hop-0 slots fold in item0 -> scalar logit0 (skip g_Rh)
//   [RB, RB+HB)    : h_all / t_all gather (float4 granularity)
//   [.., +CB)      : uEmbed + iEmbed contiguous copy (float4)
//   [.., +DB)      : dup flags, WARP-PER-B (lane-parallel scan of L1-hot pos;
//                    ~300 cycles/warp — invisible in the tail wave)
// ZERO shared memory -> full 228KB L1D carveout -> rel table gets L1 hits.
// ---------------------------------------------------------------------------
__global__ void __launch_bounds__(256) mega_kernel(
        const int*    __restrict__ pos,
        const int*    __restrict__ mh,
        const int*    __restrict__ mr,
        const int*    __restrict__ mt,
        const float4* __restrict__ uE4,
        const float4* __restrict__ iE4,
        const float4* __restrict__ ent4,
        const float4* __restrict__ rel4,
        float4* __restrict__ out_u4,
        float4* __restrict__ out_h4,
        float4* __restrict__ out_t4,
        float4* __restrict__ out_r4,
        int HBM, int RB, int HB, int CB, int Ue4, int Ie4, int BM, int B) {
    int blk = blockIdx.x;
    const float* ent = (const float*)ent4;
    const float* iE  = (const float*)iE4;
    const unsigned FULL = 0xffffffffu;

    if (blk < RB) {
        int warp = threadIdx.x >> 5, lane = threadIdx.x & 31;
        int slot = blk * 8 + warp;
        if (slot >= HBM) return;

        int r = __ldg(&mr[slot]);
        const float4* src = rel4 + (size_t)r * 256;
        float4* dst = out_r4 + (size_t)slot * 256;

        float4 v[8];
        #pragma unroll
        for (int k = 0; k < 8; k++)       // 8 outstanding loads (L1/L2)
            v[k] = __ldg(&src[k * 32 + lane]);

        int e = __ldg(&mh[slot]);
        float hval = __ldg(&ent[(size_t)e * DD + lane]);

        int c4 = (lane & 7) * 4;
        float hx = __shfl_sync(FULL, hval, c4 + 0);
        float hy = __shfl_sync(FULL, hval, c4 + 1);
        float hz = __shfl_sync(FULL, hval, c4 + 2);
        float hw = __shfl_sync(FULL, hval, c4 + 3);

        float p[8];
        #pragma unroll
        for (int k = 0; k < 8; k++) {
            __stcs(&dst[k * 32 + lane], v[k]);   // streaming write-out
            p[k] = v[k].x * hx + v[k].y * hy + v[k].z * hz + v[k].w * hw;
        }
        #pragma unroll
        for (int k = 0; k < 8; k++) {
            p[k] += __shfl_xor_sync(FULL, p[k], 1);
            p[k] += __shfl_xor_sync(FULL, p[k], 2);
            p[k] += __shfl_xor_sync(FULL, p[k], 4);
        }
        int myk = lane & 7;
        float temp = p[0];
        #pragma unroll
        for (int k = 1; k < 8; k++) if (myk == k) temp = p[k];
        float acc = __shfl_sync(FULL, temp, ((lane & 3) << 3) + (lane >> 2));

        if (slot < BM) {
            int b = slot / MM;
            int p0 = __ldg(&pos[b]);
            float it0 = __ldg(&iE[(size_t)p0 * DD + lane]);
            float lg = warpSum(acc * it0);
            if (lane == 0) g_logit0[slot] = lg;
        } else {
            g_Rh[(size_t)slot * DD + lane] = acc;
        }
    } else if (blk < RB + HB) {
        int tid = (blk - RB) * 256 + threadIdx.x;
        int N = HBM * 8;
        if (tid < N) {
            int slot = tid >> 3, j = tid & 7;
            int e = __ldg(&mh[slot]);
            __stcs(&out_h4[slot * 8 + j], __ldg(&ent4[(size_t)e * 8 + j]));
        } else if (tid < 2 * N) {
            int t2 = tid - N;
            int slot = t2 >> 3, j = t2 & 7;
            int e = __ldg(&mt[slot]);
            float4 v = __ldg(&ent4[(size_t)e * 8 + j]);
            v.x = v.x > 0.f ? v.x : LEAKY * v.x;
            v.y = v.y > 0.f ? v.y : LEAKY * v.y;
            v.z = v.z > 0.f ? v.z : LEAKY * v.z;
            v.w = v.w > 0.f ? v.w : LEAKY * v.w;
            out_t4[slot * 8 + j] = v;
        }
    } else if (blk < RB + HB + CB) {
        int j = (blk - RB - HB) * 256 + threadIdx.x;
        if (j < Ue4)
            __stcs(&out_u4[j], __ldg(&uE4[j]));
        else if (j < Ue4 + Ie4)
            __stcs(&out_u4[j], __ldg(&iE4[j - Ue4]));
    } else {
        // ---- dup flags: WARP per batch row b, lane-parallel scan ----
        int warp = threadIdx.x >> 5, lane = threadIdx.x & 31;
        int b = (blk - RB - HB - CB) * 8 + warp;
        if (b < B) {
            int p = __ldg(&pos[b]);
            bool dup = false;
            for (int j = b + 1 + lane; j < B; j += 32)
                dup |= (__ldg(&pos[j]) == p);
            int any = __any_sync(FULL, dup);
            if (lane == 0) g_dup[b] = any;
        }
    }
}

// ---------------------------------------------------------------------------
// Ripple (R16 version, measured 12.5us): one warp per b, 4 warps/block,
// 48KB smem. ALL memory the warp needs (hop-1 Rh, hop-0 t, hop-1 t = 24
// lines) issued as cp.async at instruction 0. Dup resolution is one
// broadcast load of the mega-precomputed flag.
// ---------------------------------------------------------------------------
__global__ void __launch_bounds__(128) ripple_kernel(
        const int*   __restrict__ pos,
        const float* __restrict__ iE,
        const float* __restrict__ t_all,
        const float* __restrict__ W,
        float* __restrict__ out_i,
        int B, int nhop) {
    __shared__ float sRh[RW][MM * DD];   // 16KB
    __shared__ float sT0[RW][MM * DD];   // 16KB
    __shared__ float sT1[RW][MM * DD];   // 16KB  (total 48KB)
    const unsigned FULL = 0xffffffffu;
    int warp = threadIdx.x >> 5, lane = threadIdx.x & 31;
    int b = blockIdx.x * RW + warp;
    if (b >= B) return;
    int p = __ldg(&pos[b]);

    // issue ALL prefetches first: hop-1 Rh, hop-0 t, hop-1 t (24 cp.async)
    {
        const float4* Rh4 = (const float4*)(g_Rh + (size_t)(B + b) * MM * DD);
        const float4* T0  = (const float4*)(t_all + (size_t)b * MM * DD);
        const float4* T1  = (const float4*)(t_all + (size_t)(B + b) * MM * DD);
        uint32_t aR = (uint32_t)__cvta_generic_to_shared(&sRh[warp][0]);
        uint32_t a0 = (uint32_t)__cvta_generic_to_shared(&sT0[warp][0]);
        uint32_t a1 = (uint32_t)__cvta_generic_to_shared(&sT1[warp][0]);
        #pragma unroll
        for (int j = 0; j < 8; j++) {
            cp16(a0 + (j * 32 + lane) * 16, &T0[j * 32 + lane]);
            cp16(aR + (j * 32 + lane) * 16, &Rh4[j * 32 + lane]);
            cp16(a1 + (j * 32 + lane) * 16, &T1[j * 32 + lane]);
        }
        asm volatile("cp.async.commit_group;");
    }

    float logit = __ldg(&g_logit0[(size_t)b * MM + lane]);
    float item = __ldg(&iE[(size_t)p * DD + lane]);

    // last-wins: precomputed flag (one broadcast load, overlaps the asyncs)
    if (__ldg(&g_dup[b])) {
        asm volatile("cp.async.wait_group 0;" ::: "memory");  // drain safely
        return;
    }

    const float* myRh = sRh[warp];
    for (int hop = 0; hop < nhop; hop++) {
        if (hop > 0) {
            if (hop > 1) {   // generic fallback for nhop>2 (unused @nhop=2)
                float* dRh = sRh[warp];
                float* dT1 = sT1[warp];
                const float4* Rh4 =
                    (const float4*)(g_Rh + (size_t)(hop * B + b) * MM * DD);
                const float4* T4 =
                    (const float4*)(t_all + (size_t)(hop * B + b) * MM * DD);
                #pragma unroll
                for (int j = 0; j < 8; j++) {
                    ((float4*)dRh)[j * 32 + lane] = __ldg(&Rh4[j * 32 + lane]);
                    ((float4*)dT1)[j * 32 + lane] = __ldg(&T4[j * 32 + lane]);
                }
                __syncwarp();
            }
            // logit[m] on lane m from smem Rh x shuffled item, 4 partials
            float l0 = 0.f, l1 = 0.f, l2 = 0.f, l3 = 0.f;
            #pragma unroll
            for (int i = 0; i < DD; i += 4) {
                int e0 = (i + 0 + lane) & (DD - 1);
                int e1 = (i + 1 + lane) & (DD - 1);
                int e2 = (i + 2 + lane) & (DD - 1);
                int e3 = (i + 3 + lane) & (DD - 1);
                l0 = fmaf(myRh[lane * DD + e0], __shfl_sync(FULL, item, e0), l0);
                l1 = fmaf(myRh[lane * DD + e1], __shfl_sync(FULL, item, e1), l1);
                l2 = fmaf(myRh[lane * DD + e2], __shfl_sync(FULL, item, e2), l2);
                l3 = fmaf(myRh[lane * DD + e3], __shfl_sync(FULL, item, e3), l3);
            }
            logit = (l0 + l1) + (l2 + l3);
        }
        // softmax across lanes
        float mx = warpMax(logit);
        float ex = expf(logit - mx);
        float prob = ex / warpSum(ex);

        if (hop == 0) {  // first consumption of smem tiles
            asm volatile("cp.async.wait_group 0;" ::: "memory");
            __syncwarp();
        }
        const float* tb = (hop == 0) ? sT0[warp] : sT1[warp];
        float o0 = 0.f, o1 = 0.f, o2 = 0.f, o3 = 0.f;
        #pragma unroll
        for (int m = 0; m < MM; m += 4) {
            float pa = __shfl_sync(FULL, prob, m + 0);
            float pb = __shfl_sync(FULL, prob, m + 1);
            float pc = __shfl_sync(FULL, prob, m + 2);
            float pd = __shfl_sync(FULL, prob, m + 3);
            o0 = fmaf(pa, tb[(m + 0) * DD + lane], o0);
            o1 = fmaf(pb, tb[(m + 1) * DD + lane], o1);
            o2 = fmaf(pc, tb[(m + 2) * DD + lane], o2);
            o3 = fmaf(pd, tb[(m + 3) * DD + lane], o3);
        }
        float o = (o0 + o1) + (o2 + o3);

        // item = (item + o) @ W.T : x broadcast via shuffle, W via L1 (__ldg)
        float x = item + o;
        float n0 = 0.f, n1 = 0.f, n2 = 0.f, n3 = 0.f;
        #pragma unroll
        for (int e = 0; e < DD; e += 4) {
            int e0 = (e + 0 + lane) & (DD - 1);
            int e1 = (e + 1 + lane) & (DD - 1);
            int e2 = (e + 2 + lane) & (DD - 1);
            int e3 = (e + 3 + lane) & (DD - 1);
            n0 = fmaf(__shfl_sync(FULL, x, e0), __ldg(&W[lane * DD + e0]), n0);
            n1 = fmaf(__shfl_sync(FULL, x, e1), __ldg(&W[lane * DD + e1]), n1);
            n2 = fmaf(__shfl_sync(FULL, x, e2), __ldg(&W[lane * DD + e2]), n2);
            n3 = fmaf(__shfl_sync(FULL, x, e3), __ldg(&W[lane * DD + e3]), n3);
        }
        item = (n0 + n1) + (n2 + n3);
    }
    __stcs(&out_i[(size_t)p * DD + lane], item);   // never re-read
}

// ---------------------------------------------------------------------------
extern "C" void kernel_launch(void* const* d_in, const int* in_sizes, int n_in,
                              void* d_out, int out_size) {
    const int*   pos = (const int*)d_in[0];
    const int*   mh  = (const int*)d_in[1];
    const int*   mr  = (const int*)d_in[2];
    const int*   mt  = (const int*)d_in[3];
    const float* uE  = (const float*)d_in[4];
    const float* iE  = (const float*)d_in[5];
    const float* ent = (const float*)d_in[6];
    const float* rel = (const float*)d_in[7];
    const float* W   = (const float*)d_in[8];
    float* out = (float*)d_out;

    const int B    = in_sizes[0];             // 2048
    const int HBM  = in_sizes[1];             // H*B*M = 131072
    const int nhop = HBM / (B * MM);          // 2
    const int BM   = B * MM;                  // 65536
    const size_t Ue = (size_t)in_sizes[4];    // USER*D floats
    const size_t Ie = (size_t)in_sizes[5];    // ITEM*D floats

    float* out_u = out;
    float* out_i = out_u + Ue;
    float* out_h = out_i + Ie;
    float* out_t = out_h + (size_t)HBM * DD;
    float* out_r = out_t + (size_t)HBM * DD;

    const int RB  = (HBM + 7) / 8;                      // 16384 r-blocks
    const int HB  = (2 * HBM * 8 + 255) / 256;          // 8192 ht-blocks
    const int Ue4 = (int)(Ue / 4), Ie4 = (int)(Ie / 4);
    const int CB  = (Ue4 + Ie4 + 255) / 256;            // 6250 copy-blocks
    const int DB  = (B + 7) / 8;                        // 256 dup-blocks (warp/b)

    mega_kernel<<<RB + HB + CB + DB, 256>>>(
        pos, mh, mr, mt,
        (const float4*)uE, (const float4*)iE,
        (const float4*)ent, (const float4*)rel,
        (float4*)out_u, (float4*)out_h, (float4*)out_t, (float4*)out_r,
        HBM, RB, HB, CB, Ue4, Ie4, BM, B);

    ripple_kernel<<<(B + RW - 1) / RW, 128>>>(pos, iE, out_t, W, out_i, B, nhop);
}